// round 4
// baseline (speedup 1.0000x reference)
#include <cuda_runtime.h>

#define N_NODES  100000
#define N_EDGES  3200000
#define D_FEAT   64
#define CHUNKS   16          // 64 floats = 16 float4
#define SCAN_T   1024
#define PER_T    ((N_NODES + SCAN_T - 1) / SCAN_T)   // 98

// ------------------------- device scratch (no allocs) -----------------------
// g_counts is zero-initialized at module load; k_scan re-zeroes it after use,
// so every kernel_launch (and every graph replay) starts with counts == 0.
__device__ int   g_counts[N_NODES];
__device__ int   g_rowptr[N_NODES + 1];
__device__ int   g_cursor[N_NODES];
__device__ uint2 g_colval[N_EDGES];     // packed (col, val_bits) per CSR slot

// ---------------------------------------------------------------------------
// 1) histogram of rows (4 edges per thread via int4)
// ---------------------------------------------------------------------------
__global__ void k_hist(const int4* __restrict__ erow4) {
    int i = blockIdx.x * blockDim.x + threadIdx.x;
    if (i >= N_EDGES / 4) return;
    int4 r = __ldg(&erow4[i]);
    atomicAdd(&g_counts[r.x], 1);
    atomicAdd(&g_counts[r.y], 1);
    atomicAdd(&g_counts[r.z], 1);
    atomicAdd(&g_counts[r.w], 1);
}

// ---------------------------------------------------------------------------
// 2) single-block exclusive scan of all 100K counts.
//    Each thread owns PER_T contiguous elements: sum -> block scan of totals
//    -> second pass writes exclusive prefixes into rowptr & cursor and
//    zeroes counts (ready for the next replay).
// ---------------------------------------------------------------------------
__global__ void k_scan() {
    __shared__ int s[SCAN_T];
    int t = threadIdx.x;
    int base = t * PER_T;

    // pass 1: per-thread sum
    int sum = 0;
    #pragma unroll 7
    for (int k = 0; k < PER_T; k++) {
        int idx = base + k;
        if (idx < N_NODES) sum += g_counts[idx];
    }
    s[t] = sum;
    __syncthreads();

    // Hillis-Steele inclusive scan over 1024 thread totals
    #pragma unroll
    for (int off = 1; off < SCAN_T; off <<= 1) {
        int a = (t >= off) ? s[t - off] : 0;
        __syncthreads();
        s[t] += a;
        __syncthreads();
    }
    int running = s[t] - sum;   // exclusive offset for this thread's chunk

    // pass 2: write exclusive prefixes, init cursors, zero counts
    #pragma unroll 7
    for (int k = 0; k < PER_T; k++) {
        int idx = base + k;
        if (idx < N_NODES) {
            int c = g_counts[idx];
            g_rowptr[idx] = running;
            g_cursor[idx] = running;
            g_counts[idx] = 0;
            running += c;
        }
    }
    if (t == 0) g_rowptr[N_NODES] = N_EDGES;
}

// ---------------------------------------------------------------------------
// 3) bucket-scatter edges into CSR slots (4 edges per thread)
// ---------------------------------------------------------------------------
__global__ void k_scatter(const int4* __restrict__ erow4,
                          const int4* __restrict__ ecol4,
                          const float4* __restrict__ eval4) {
    int i = blockIdx.x * blockDim.x + threadIdx.x;
    if (i >= N_EDGES / 4) return;
    int4   r = __ldg(&erow4[i]);
    int4   c = __ldg(&ecol4[i]);
    float4 v = __ldg(&eval4[i]);

    int p0 = atomicAdd(&g_cursor[r.x], 1);
    g_colval[p0] = make_uint2((unsigned)c.x, __float_as_uint(v.x));
    int p1 = atomicAdd(&g_cursor[r.y], 1);
    g_colval[p1] = make_uint2((unsigned)c.y, __float_as_uint(v.y));
    int p2 = atomicAdd(&g_cursor[r.z], 1);
    g_colval[p2] = make_uint2((unsigned)c.z, __float_as_uint(v.z));
    int p3 = atomicAdd(&g_cursor[r.w], 1);
    g_colval[p3] = make_uint2((unsigned)c.w, __float_as_uint(v.w));
}

// ---------------------------------------------------------------------------
// 4) pull phase: 16 threads per node, one float4 chunk each.
//    Register accumulation, coalesced store, zero atomics.
// ---------------------------------------------------------------------------
__global__ void k_pull(const float4* __restrict__ x4, float4* __restrict__ out4) {
    int gid = blockIdx.x * blockDim.x + threadIdx.x;
    int n = gid >> 4;            // node
    int c = gid & 15;            // float4 chunk
    if (n >= N_NODES) return;

    int j   = g_rowptr[n];
    int end = g_rowptr[n + 1];

    float4 acc = make_float4(0.f, 0.f, 0.f, 0.f);

    // unroll by 4 for memory-level parallelism
    for (; j + 4 <= end; j += 4) {
        uint2 cv0 = __ldg(&g_colval[j]);
        uint2 cv1 = __ldg(&g_colval[j + 1]);
        uint2 cv2 = __ldg(&g_colval[j + 2]);
        uint2 cv3 = __ldg(&g_colval[j + 3]);
        float4 x0 = __ldg(&x4[(long long)cv0.x * CHUNKS + c]);
        float4 x1 = __ldg(&x4[(long long)cv1.x * CHUNKS + c]);
        float4 x2 = __ldg(&x4[(long long)cv2.x * CHUNKS + c]);
        float4 x3 = __ldg(&x4[(long long)cv3.x * CHUNKS + c]);
        float v0 = __uint_as_float(cv0.y);
        float v1 = __uint_as_float(cv1.y);
        float v2 = __uint_as_float(cv2.y);
        float v3 = __uint_as_float(cv3.y);
        acc.x += v0 * x0.x + v1 * x1.x + v2 * x2.x + v3 * x3.x;
        acc.y += v0 * x0.y + v1 * x1.y + v2 * x2.y + v3 * x3.y;
        acc.z += v0 * x0.z + v1 * x1.z + v2 * x2.z + v3 * x3.z;
        acc.w += v0 * x0.w + v1 * x1.w + v2 * x2.w + v3 * x3.w;
    }
    for (; j < end; j++) {
        uint2 cv = __ldg(&g_colval[j]);
        float4 xv = __ldg(&x4[(long long)cv.x * CHUNKS + c]);
        float v = __uint_as_float(cv.y);
        acc.x += v * xv.x;
        acc.y += v * xv.y;
        acc.z += v * xv.z;
        acc.w += v * xv.w;
    }

    out4[(long long)n * CHUNKS + c] = acc;
}

// ---------------------------------------------------------------------------
extern "C" void kernel_launch(void* const* d_in, const int* in_sizes, int n_in,
                              void* d_out, int out_size) {
    // Input order: t, x, edge_row, edge_col, edge_val
    const float* x    = (const float*)d_in[1];
    const int*   erow = (const int*)d_in[2];
    const int*   ecol = (const int*)d_in[3];
    const float* ev   = (const float*)d_in[4];
    float*       out  = (float*)d_out;

    const int T = 256;
    const int Q = N_EDGES / 4;   // 800K

    k_hist<<<(Q + T - 1) / T, T>>>((const int4*)erow);
    k_scan<<<1, SCAN_T>>>();
    k_scatter<<<(Q + T - 1) / T, T>>>((const int4*)erow, (const int4*)ecol,
                                      (const float4*)ev);

    long long pull_threads = (long long)N_NODES * CHUNKS;   // 1.6M
    k_pull<<<(int)((pull_threads + T - 1) / T), T>>>((const float4*)x, (float4*)out);
}

// round 5
// speedup vs baseline: 2.4297x; 2.4297x over previous
#include <cuda_runtime.h>

#define N_NODES  100000
#define N_EDGES  3200000
#define D_FEAT   64
#define CHUNKS   16          // 64 floats = 16 float4
#define SCAN_BLK 1024
#define N_SCANB  ((N_NODES + SCAN_BLK - 1) / SCAN_BLK)   // 98

// ------------------------- device scratch (no allocs) -----------------------
// g_counts starts zeroed (module load) and is re-zeroed by k_scanA each call,
// so every graph replay starts clean.
__device__ int   g_counts[N_NODES];
__device__ int   g_rowptr[N_NODES + 1];
__device__ int   g_cursor[N_NODES];
__device__ int   g_blocksum[128];
__device__ uint2 g_colval[N_EDGES];     // packed (col, val_bits) per CSR slot

// ---------------------------------------------------------------------------
// 1) histogram of rows (4 edges per thread via int4)
// ---------------------------------------------------------------------------
__global__ void k_hist(const int4* __restrict__ erow4) {
    int i = blockIdx.x * blockDim.x + threadIdx.x;
    if (i >= N_EDGES / 4) return;
    int4 r = __ldg(&erow4[i]);
    atomicAdd(&g_counts[r.x], 1);
    atomicAdd(&g_counts[r.y], 1);
    atomicAdd(&g_counts[r.z], 1);
    atomicAdd(&g_counts[r.w], 1);
}

// ---------------------------------------------------------------------------
// 2a) coalesced per-block exclusive scan; emits block totals; zeroes counts
// ---------------------------------------------------------------------------
__global__ void k_scanA() {
    __shared__ int s[SCAN_BLK];
    int t = threadIdx.x;
    int i = blockIdx.x * SCAN_BLK + t;
    int v = 0;
    if (i < N_NODES) {
        v = g_counts[i];
        g_counts[i] = 0;            // ready for next replay
    }
    s[t] = v;
    __syncthreads();
    #pragma unroll
    for (int off = 1; off < SCAN_BLK; off <<= 1) {
        int a = (t >= off) ? s[t - off] : 0;
        __syncthreads();
        s[t] += a;
        __syncthreads();
    }
    if (i < N_NODES) g_rowptr[i] = s[t] - v;      // exclusive within block
    if (t == SCAN_BLK - 1) g_blocksum[blockIdx.x] = s[t];
}

// ---------------------------------------------------------------------------
// 2b) every block scans the 98 block totals in smem, adds its own offset,
//     writes final rowptr + cursor. Fuses old scan2+scan3.
// ---------------------------------------------------------------------------
__global__ void k_scanB() {
    __shared__ int s[128];
    int t = threadIdx.x;
    if (t < 128) s[t] = (t < N_SCANB) ? g_blocksum[t] : 0;
    __syncthreads();
    #pragma unroll
    for (int off = 1; off < 128; off <<= 1) {
        int a = (t < 128 && t >= off) ? s[t - off] : 0;
        __syncthreads();
        if (t < 128) s[t] += a;
        __syncthreads();
    }
    int b = blockIdx.x;
    int boff = (b == 0) ? 0 : s[b - 1];           // exclusive block offset
    int i = b * SCAN_BLK + t;
    if (i < N_NODES) {
        int r = g_rowptr[i] + boff;
        g_rowptr[i] = r;
        g_cursor[i] = r;
    }
    if (b == 0 && t == 0) g_rowptr[N_NODES] = N_EDGES;
}

// ---------------------------------------------------------------------------
// 3) bucket-scatter edges into CSR slots (4 edges per thread)
// ---------------------------------------------------------------------------
__global__ void k_scatter(const int4* __restrict__ erow4,
                          const int4* __restrict__ ecol4,
                          const float4* __restrict__ eval4) {
    int i = blockIdx.x * blockDim.x + threadIdx.x;
    if (i >= N_EDGES / 4) return;
    int4   r = __ldg(&erow4[i]);
    int4   c = __ldg(&ecol4[i]);
    float4 v = __ldg(&eval4[i]);

    int p0 = atomicAdd(&g_cursor[r.x], 1);
    g_colval[p0] = make_uint2((unsigned)c.x, __float_as_uint(v.x));
    int p1 = atomicAdd(&g_cursor[r.y], 1);
    g_colval[p1] = make_uint2((unsigned)c.y, __float_as_uint(v.y));
    int p2 = atomicAdd(&g_cursor[r.z], 1);
    g_colval[p2] = make_uint2((unsigned)c.z, __float_as_uint(v.z));
    int p3 = atomicAdd(&g_cursor[r.w], 1);
    g_colval[p3] = make_uint2((unsigned)c.w, __float_as_uint(v.w));
}

// ---------------------------------------------------------------------------
// 4) pull phase: 16 threads per node, one float4 chunk each.
//    Register accumulation, coalesced store, zero atomics.
// ---------------------------------------------------------------------------
__global__ void k_pull(const float4* __restrict__ x4, float4* __restrict__ out4) {
    int gid = blockIdx.x * blockDim.x + threadIdx.x;
    int n = gid >> 4;            // node
    int c = gid & 15;            // float4 chunk
    if (n >= N_NODES) return;

    int j   = g_rowptr[n];
    int end = g_rowptr[n + 1];

    float4 acc = make_float4(0.f, 0.f, 0.f, 0.f);

    // unroll by 4 for memory-level parallelism
    for (; j + 4 <= end; j += 4) {
        uint2 cv0 = __ldg(&g_colval[j]);
        uint2 cv1 = __ldg(&g_colval[j + 1]);
        uint2 cv2 = __ldg(&g_colval[j + 2]);
        uint2 cv3 = __ldg(&g_colval[j + 3]);
        float4 x0 = __ldg(&x4[(long long)cv0.x * CHUNKS + c]);
        float4 x1 = __ldg(&x4[(long long)cv1.x * CHUNKS + c]);
        float4 x2 = __ldg(&x4[(long long)cv2.x * CHUNKS + c]);
        float4 x3 = __ldg(&x4[(long long)cv3.x * CHUNKS + c]);
        float v0 = __uint_as_float(cv0.y);
        float v1 = __uint_as_float(cv1.y);
        float v2 = __uint_as_float(cv2.y);
        float v3 = __uint_as_float(cv3.y);
        acc.x += v0 * x0.x + v1 * x1.x + v2 * x2.x + v3 * x3.x;
        acc.y += v0 * x0.y + v1 * x1.y + v2 * x2.y + v3 * x3.y;
        acc.z += v0 * x0.z + v1 * x1.z + v2 * x2.z + v3 * x3.z;
        acc.w += v0 * x0.w + v1 * x1.w + v2 * x2.w + v3 * x3.w;
    }
    for (; j < end; j++) {
        uint2 cv = __ldg(&g_colval[j]);
        float4 xv = __ldg(&x4[(long long)cv.x * CHUNKS + c]);
        float v = __uint_as_float(cv.y);
        acc.x += v * xv.x;
        acc.y += v * xv.y;
        acc.z += v * xv.z;
        acc.w += v * xv.w;
    }

    out4[(long long)n * CHUNKS + c] = acc;
}

// ---------------------------------------------------------------------------
extern "C" void kernel_launch(void* const* d_in, const int* in_sizes, int n_in,
                              void* d_out, int out_size) {
    // Input order: t, x, edge_row, edge_col, edge_val
    const float* x    = (const float*)d_in[1];
    const int*   erow = (const int*)d_in[2];
    const int*   ecol = (const int*)d_in[3];
    const float* ev   = (const float*)d_in[4];
    float*       out  = (float*)d_out;

    const int T = 256;
    const int Q = N_EDGES / 4;   // 800K

    k_hist<<<(Q + T - 1) / T, T>>>((const int4*)erow);
    k_scanA<<<N_SCANB, SCAN_BLK>>>();
    k_scanB<<<N_SCANB, SCAN_BLK>>>();
    k_scatter<<<(Q + T - 1) / T, T>>>((const int4*)erow, (const int4*)ecol,
                                      (const float4*)ev);

    long long pull_threads = (long long)N_NODES * CHUNKS;   // 1.6M
    k_pull<<<(int)((pull_threads + T - 1) / T), T>>>((const float4*)x, (float4*)out);
}